// round 1
// baseline (speedup 1.0000x reference)
#include <cuda_runtime.h>
#include <math.h>

#define BATCH 4
#define SEQ   4096
#define EMB   1024
#define HDIM  128

// scratch for projections (allocation-free: __device__ globals)
__device__ float g_Q[(size_t)BATCH * SEQ * HDIM];
__device__ float g_K[(size_t)BATCH * SEQ * HDIM];
__device__ float g_V[(size_t)BATCH * SEQ * HDIM];

// ---------------------------------------------------------------------------
// Projection GEMM: out[m][n] = sum_e x[m][e] * W[n][e]
// M = BATCH*SEQ = 16384, N = HDIM = 128, K = EMB = 1024
// Tile 128x128x16, 256 threads, 8x8 register blocking.
// blockIdx.y selects which of (Wk, Wq, Wv).
// ---------------------------------------------------------------------------
__global__ __launch_bounds__(256) void proj_kernel(
    const float* __restrict__ x,
    const float* __restrict__ Wk,
    const float* __restrict__ Wq,
    const float* __restrict__ Wv)
{
    __shared__ float Xs[16][132];   // [k][m], padded to break store conflicts
    __shared__ float Ws[16][132];   // [k][n]

    const int which = blockIdx.y;
    const float* W = (which == 0) ? Wk : (which == 1) ? Wq : Wv;
    float* out = (which == 0) ? g_K : (which == 1) ? g_Q : g_V;

    const int m0  = blockIdx.x * 128;
    const int tid = threadIdx.x;
    const int tx  = tid & 15;       // 0..15  (n groups of 8)
    const int ty  = tid >> 4;       // 0..15  (m groups of 8)

    float acc[8][8];
#pragma unroll
    for (int i = 0; i < 8; i++)
#pragma unroll
        for (int j = 0; j < 8; j++) acc[i][j] = 0.0f;

    for (int e0 = 0; e0 < EMB; e0 += 16) {
        __syncthreads();
        // load tiles (transposed into [k][row]) — global reads coalesced
#pragma unroll
        for (int i = 0; i < 8; i++) {
            int idx = tid + i * 256;        // 0..2047
            int k = idx & 15;
            int r = idx >> 4;               // 0..127
            Xs[k][r] = x[(size_t)(m0 + r) * EMB + e0 + k];
            Ws[k][r] = W[(size_t)r * EMB + e0 + k];
        }
        __syncthreads();

#pragma unroll
        for (int k = 0; k < 16; k++) {
            float a[8], bb[8];
            *(float4*)&a[0]  = *(const float4*)&Xs[k][ty * 8];
            *(float4*)&a[4]  = *(const float4*)&Xs[k][ty * 8 + 4];
            *(float4*)&bb[0] = *(const float4*)&Ws[k][tx * 8];
            *(float4*)&bb[4] = *(const float4*)&Ws[k][tx * 8 + 4];
#pragma unroll
            for (int i = 0; i < 8; i++)
#pragma unroll
                for (int j = 0; j < 8; j++)
                    acc[i][j] = fmaf(a[i], bb[j], acc[i][j]);
        }
    }

    // write 8x8 tile
#pragma unroll
    for (int i = 0; i < 8; i++) {
        size_t row = (size_t)(m0 + ty * 8 + i) * HDIM + tx * 8;
        *(float4*)&out[row]     = make_float4(acc[i][0], acc[i][1], acc[i][2], acc[i][3]);
        *(float4*)&out[row + 4] = make_float4(acc[i][4], acc[i][5], acc[i][6], acc[i][7]);
    }
}

// ---------------------------------------------------------------------------
// Flash attention (causal), BQ=64 query rows, BK=64 key rows per iteration.
// 256 threads: thread (ty,tx) with tx=tid%16, ty=tid/16 owns
//   S sub-tile rows 4*ty..+4, cols 4*tx..+4 ; O sub-tile rows 4*ty..+4, cols 8*tx..+8
// Work pairing: block with pair index p handles q-tiles p and 63-p
// -> every block does exactly 65 key-tile iterations (perfect balance).
// ---------------------------------------------------------------------------
#define QK_PAD 68   // row stride (floats) for transposed Q/K tiles

extern __shared__ float smem_attn[];

__global__ __launch_bounds__(256) void attn_kernel(
    const float* __restrict__ Q,
    const float* __restrict__ K,
    const float* __restrict__ V,
    float* __restrict__ out)
{
    float* Qt = smem_attn;                  // [128][QK_PAD]  Qt[d*QK_PAD + r]
    float* Kt = Qt + 128 * QK_PAD;          // [128][QK_PAD]
    float* Vs = Kt + 128 * QK_PAD;          // [64][128] row-major
    float* Ps = Vs + 64 * 128;              // [64][64]

    const int b    = blockIdx.y;
    const int pair = blockIdx.x;            // 0..31
    const int tid  = threadIdx.x;
    const int tx   = tid & 15;
    const int ty   = tid >> 4;

    const size_t base = (size_t)b * SEQ * HDIM;
    const float* Qb = Q + base;
    const float* Kb = K + base;
    const float* Vb = V + base;

    for (int half = 0; half < 2; half++) {
        const int qt = (half == 0) ? pair : (63 - pair);

        __syncthreads();
        // load Q tile transposed, pre-scaled by EMB^-0.5 = 1/32
#pragma unroll
        for (int i = 0; i < 32; i++) {
            int idx = tid + i * 256;        // 0..8191
            int d = idx & 127;
            int r = idx >> 7;
            Qt[d * QK_PAD + r] = Qb[(size_t)(qt * 64 + r) * HDIM + d] * 0.03125f;
        }

        float o[4][8];
        float m_i[4], l_i[4];
#pragma unroll
        for (int i = 0; i < 4; i++) {
            m_i[i] = -INFINITY;
            l_i[i] = 0.0f;
#pragma unroll
            for (int c = 0; c < 8; c++) o[i][c] = 0.0f;
        }

        for (int kt = 0; kt <= qt; kt++) {
            __syncthreads();   // previous PV / Q-load complete before overwrite
            // load K tile transposed
#pragma unroll
            for (int i = 0; i < 32; i++) {
                int idx = tid + i * 256;
                int d = idx & 127;
                int r = idx >> 7;
                Kt[d * QK_PAD + r] = Kb[(size_t)(kt * 64 + r) * HDIM + d];
            }
            // load V tile row-major (float4 copy)
            const float4* vsrc = (const float4*)(Vb + (size_t)(kt * 64) * HDIM);
            float4* vdst = (float4*)Vs;
#pragma unroll
            for (int i = 0; i < 8; i++) {
                int idx4 = tid + i * 256;   // 0..2047
                vdst[idx4] = vsrc[idx4];
            }
            __syncthreads();

            // ---- S = Q K^T (64x64), this thread: 4x4 ----
            float s[4][4];
#pragma unroll
            for (int i = 0; i < 4; i++)
#pragma unroll
                for (int j = 0; j < 4; j++) s[i][j] = 0.0f;

            const float* qbase = Qt + ty * 4;
            const float* kbase = Kt + tx * 4;
#pragma unroll 8
            for (int d = 0; d < 128; d++) {
                float4 a  = *(const float4*)(qbase + d * QK_PAD);
                float4 bb = *(const float4*)(kbase + d * QK_PAD);
                s[0][0] = fmaf(a.x, bb.x, s[0][0]); s[0][1] = fmaf(a.x, bb.y, s[0][1]);
                s[0][2] = fmaf(a.x, bb.z, s[0][2]); s[0][3] = fmaf(a.x, bb.w, s[0][3]);
                s[1][0] = fmaf(a.y, bb.x, s[1][0]); s[1][1] = fmaf(a.y, bb.y, s[1][1]);
                s[1][2] = fmaf(a.y, bb.z, s[1][2]); s[1][3] = fmaf(a.y, bb.w, s[1][3]);
                s[2][0] = fmaf(a.z, bb.x, s[2][0]); s[2][1] = fmaf(a.z, bb.y, s[2][1]);
                s[2][2] = fmaf(a.z, bb.z, s[2][2]); s[2][3] = fmaf(a.z, bb.w, s[2][3]);
                s[3][0] = fmaf(a.w, bb.x, s[3][0]); s[3][1] = fmaf(a.w, bb.y, s[3][1]);
                s[3][2] = fmaf(a.w, bb.z, s[3][2]); s[3][3] = fmaf(a.w, bb.w, s[3][3]);
            }

            // causal mask on the diagonal tile
            if (kt == qt) {
#pragma unroll
                for (int i = 0; i < 4; i++)
#pragma unroll
                    for (int j = 0; j < 4; j++)
                        if (4 * tx + j > 4 * ty + i) s[i][j] = -INFINITY;
            }

            // ---- online softmax ----
            float rmax[4];
#pragma unroll
            for (int i = 0; i < 4; i++) {
                rmax[i] = fmaxf(fmaxf(s[i][0], s[i][1]), fmaxf(s[i][2], s[i][3]));
            }
#pragma unroll
            for (int off = 8; off >= 1; off >>= 1)
#pragma unroll
                for (int i = 0; i < 4; i++)
                    rmax[i] = fmaxf(rmax[i], __shfl_xor_sync(0xffffffffu, rmax[i], off));

            float alpha[4], rsum[4];
#pragma unroll
            for (int i = 0; i < 4; i++) {
                float mnew = fmaxf(m_i[i], rmax[i]);
                alpha[i] = __expf(m_i[i] - mnew);   // exp(-inf)=0 on first tile
                m_i[i] = mnew;
                float p0 = __expf(s[i][0] - mnew);
                float p1 = __expf(s[i][1] - mnew);
                float p2 = __expf(s[i][2] - mnew);
                float p3 = __expf(s[i][3] - mnew);
                rsum[i] = (p0 + p1) + (p2 + p3);
                *(float4*)&Ps[(4 * ty + i) * 64 + 4 * tx] = make_float4(p0, p1, p2, p3);
            }
#pragma unroll
            for (int off = 8; off >= 1; off >>= 1)
#pragma unroll
                for (int i = 0; i < 4; i++)
                    rsum[i] += __shfl_xor_sync(0xffffffffu, rsum[i], off);
#pragma unroll
            for (int i = 0; i < 4; i++) {
                l_i[i] = l_i[i] * alpha[i] + rsum[i];
#pragma unroll
                for (int c = 0; c < 8; c++) o[i][c] *= alpha[i];
            }
            __syncthreads();   // Ps visible to all

            // ---- O += P V ----
            const float* pbase = Ps + ty * 4 * 64;
            const float* vbase = Vs + tx * 8;
#pragma unroll 4
            for (int j = 0; j < 64; j++) {
                float p0 = pbase[j];
                float p1 = pbase[64 + j];
                float p2 = pbase[128 + j];
                float p3 = pbase[192 + j];
                float4 v0 = *(const float4*)(vbase + j * 128);
                float4 v1 = *(const float4*)(vbase + j * 128 + 4);
                o[0][0] = fmaf(p0, v0.x, o[0][0]); o[0][1] = fmaf(p0, v0.y, o[0][1]);
                o[0][2] = fmaf(p0, v0.z, o[0][2]); o[0][3] = fmaf(p0, v0.w, o[0][3]);
                o[0][4] = fmaf(p0, v1.x, o[0][4]); o[0][5] = fmaf(p0, v1.y, o[0][5]);
                o[0][6] = fmaf(p0, v1.z, o[0][6]); o[0][7] = fmaf(p0, v1.w, o[0][7]);
                o[1][0] = fmaf(p1, v0.x, o[1][0]); o[1][1] = fmaf(p1, v0.y, o[1][1]);
                o[1][2] = fmaf(p1, v0.z, o[1][2]); o[1][3] = fmaf(p1, v0.w, o[1][3]);
                o[1][4] = fmaf(p1, v1.x, o[1][4]); o[1][5] = fmaf(p1, v1.y, o[1][5]);
                o[1][6] = fmaf(p1, v1.z, o[1][6]); o[1][7] = fmaf(p1, v1.w, o[1][7]);
                o[2][0] = fmaf(p2, v0.x, o[2][0]); o[2][1] = fmaf(p2, v0.y, o[2][1]);
                o[2][2] = fmaf(p2, v0.z, o[2][2]); o[2][3] = fmaf(p2, v0.w, o[2][3]);
                o[2][4] = fmaf(p2, v1.x, o[2][4]); o[2][5] = fmaf(p2, v1.y, o[2][5]);
                o[2][6] = fmaf(p2, v1.z, o[2][6]); o[2][7] = fmaf(p2, v1.w, o[2][7]);
                o[3][0] = fmaf(p3, v0.x, o[3][0]); o[3][1] = fmaf(p3, v0.y, o[3][1]);
                o[3][2] = fmaf(p3, v0.z, o[3][2]); o[3][3] = fmaf(p3, v0.w, o[3][3]);
                o[3][4] = fmaf(p3, v1.x, o[3][4]); o[3][5] = fmaf(p3, v1.y, o[3][5]);
                o[3][6] = fmaf(p3, v1.z, o[3][6]); o[3][7] = fmaf(p3, v1.w, o[3][7]);
            }
        }

        // ---- epilogue: O / l, write out ----
#pragma unroll
        for (int i = 0; i < 4; i++) {
            float inv = 1.0f / l_i[i];
            size_t row = base + (size_t)(qt * 64 + 4 * ty + i) * HDIM + tx * 8;
            *(float4*)&out[row]     = make_float4(o[i][0] * inv, o[i][1] * inv,
                                                  o[i][2] * inv, o[i][3] * inv);
            *(float4*)&out[row + 4] = make_float4(o[i][4] * inv, o[i][5] * inv,
                                                  o[i][6] * inv, o[i][7] * inv);
        }
    }
}

// ---------------------------------------------------------------------------
extern "C" void kernel_launch(void* const* d_in, const int* in_sizes, int n_in,
                              void* d_out, int out_size)
{
    const float* x  = (const float*)d_in[0];
    const float* Wk = (const float*)d_in[1];
    const float* Wq = (const float*)d_in[2];
    const float* Wv = (const float*)d_in[3];
    float* out = (float*)d_out;

    // projections: 128 M-tiles x 3 weights
    proj_kernel<<<dim3(128, 3), 256>>>(x, Wk, Wq, Wv);

    // resolve device-global scratch addresses (host API, capture-safe)
    static float *pQ = nullptr, *pK = nullptr, *pV = nullptr;
    if (!pQ) {
        cudaGetSymbolAddress((void**)&pQ, g_Q);
        cudaGetSymbolAddress((void**)&pK, g_K);
        cudaGetSymbolAddress((void**)&pV, g_V);
    }

    const size_t smem_bytes = (size_t)(128 * QK_PAD * 2 + 64 * 128 + 64 * 64) * sizeof(float);
    static bool attr_set = false;
    if (!attr_set) {
        cudaFuncSetAttribute(attn_kernel, cudaFuncAttributeMaxDynamicSharedMemorySize,
                             (int)smem_bytes);
        attr_set = true;
    }

    attn_kernel<<<dim3(32, BATCH), 256, smem_bytes>>>(pQ, pK, pV, out);
}